// round 1
// baseline (speedup 1.0000x reference)
#include <cuda_runtime.h>
#include <cstdint>
#include <cstddef>

// ---------------- problem constants ----------------
#define BATCH 256
#define C1 256            // conv1 out channels
#define H1 20             // conv1 out spatial
#define C2 256            // conv2 out channels
#define H2 6
#define KS 9
#define NPOS 36           // 6*6
#define KDIM 20736        // 256*81
#define NDIM 9216         // 256*36
#define MDIM 256
#define NCAPS 1152
#define VIN 8
#define NOUT 10
#define VOUT 16

// ---------------- scratch (device globals; allocation-free) ----------------
__device__ float g_h[(size_t)BATCH * C1 * H1 * H1];          // 26.2M  (conv1 out)
__device__ float g_col[(size_t)KDIM * NDIM];                  // 191.1M (im2col)
__device__ float g_c2[(size_t)MDIM * NDIM];                   // 2.36M  (gemm out)
__device__ float g_caps[(size_t)BATCH * NCAPS * VIN];         // 2.36M
__device__ float g_uhat[(size_t)BATCH * NCAPS * NOUT * VOUT]; // 47.2M

// ---------------- conv1: [B,1,28,28] -> [B,256,20,20] ----------------
__global__ void conv1_kernel(const float* __restrict__ x,
                             const float* __restrict__ w,
                             const float* __restrict__ bias) {
    int b = blockIdx.x;
    __shared__ float img[28 * 28];
    __shared__ float ws[8 * 81];
    int tid = threadIdx.x;  // 400 threads
    for (int i = tid; i < 784; i += 400) img[i] = x[(size_t)b * 784 + i];
    int y = tid / 20, xx = tid % 20;
    for (int oc0 = 0; oc0 < C1; oc0 += 8) {
        __syncthreads();
        for (int i = tid; i < 8 * 81; i += 400) ws[i] = w[oc0 * 81 + i];
        __syncthreads();
        float acc[8];
#pragma unroll
        for (int o = 0; o < 8; o++) acc[o] = bias[oc0 + o];
#pragma unroll
        for (int r = 0; r < 9; r++) {
#pragma unroll
            for (int s = 0; s < 9; s++) {
                float iv = img[(y + r) * 28 + xx + s];
                int k = r * 9 + s;
#pragma unroll
                for (int o = 0; o < 8; o++) acc[o] += iv * ws[o * 81 + k];
            }
        }
#pragma unroll
        for (int o = 0; o < 8; o++)
            g_h[((size_t)b * C1 + oc0 + o) * 400 + tid] = acc[o];
    }
}

// ---------------- im2col for conv2 (stride 2, 9x9) ----------------
__global__ void im2col_kernel() {
    size_t idx = (size_t)blockIdx.x * blockDim.x + threadIdx.x;
    const size_t total = (size_t)KDIM * NDIM;
    if (idx >= total) return;
    int n = (int)(idx % NDIM);
    int k = (int)(idx / NDIM);
    int ic = k / 81;
    int rs = k % 81;
    int r = rs / 9, s = rs % 9;
    int b = n / NPOS;
    int p = n % NPOS;
    int py = p / 6, px = p % 6;
    g_col[idx] = g_h[(((size_t)b * C1 + ic) * H1 + 2 * py + r) * H1 + (2 * px + s)];
}

// ---------------- SGEMM: C[256,9216] = A[256,20736] * B[20736,9216] ----------------
#define BM 128
#define BN 128
#define BK 8
__global__ __launch_bounds__(256) void sgemm_kernel(const float* __restrict__ A) {
    __shared__ float As[BK][BM];
    __shared__ float Bs[BK][BN];
    int bx = blockIdx.x;  // n tile (0..71)
    int by = blockIdx.y;  // m tile (0..1)
    int tid = threadIdx.x;
    int tx = tid % 16, ty = tid / 16;

    const float* Ap = A + (size_t)by * BM * KDIM;
    const float* Bp = g_col + (size_t)bx * BN;

    int arow = tid / 2, acol = (tid % 2) * 4;
    int brow = tid / 32, bcol = (tid % 32) * 4;

    float acc[8][8];
#pragma unroll
    for (int i = 0; i < 8; i++)
#pragma unroll
        for (int j = 0; j < 8; j++) acc[i][j] = 0.f;

    for (int k0 = 0; k0 < KDIM; k0 += BK) {
        float4 av = *(const float4*)(Ap + (size_t)arow * KDIM + k0 + acol);
        float4 bv = *(const float4*)(Bp + (size_t)(k0 + brow) * NDIM + bcol);
        As[acol + 0][arow] = av.x;
        As[acol + 1][arow] = av.y;
        As[acol + 2][arow] = av.z;
        As[acol + 3][arow] = av.w;
        *(float4*)&Bs[brow][bcol] = bv;
        __syncthreads();
#pragma unroll
        for (int k = 0; k < BK; k++) {
            float am[8], bn[8];
#pragma unroll
            for (int i = 0; i < 8; i++) am[i] = As[k][ty * 8 + i];
#pragma unroll
            for (int j = 0; j < 8; j++) bn[j] = Bs[k][tx * 8 + j];
#pragma unroll
            for (int i = 0; i < 8; i++)
#pragma unroll
                for (int j = 0; j < 8; j++) acc[i][j] += am[i] * bn[j];
        }
        __syncthreads();
    }
#pragma unroll
    for (int i = 0; i < 8; i++) {
        int m = by * BM + ty * 8 + i;
        float* outp = g_c2 + (size_t)m * NDIM + bx * BN + tx * 8;
        *(float4*)(outp + 0) = make_float4(acc[i][0], acc[i][1], acc[i][2], acc[i][3]);
        *(float4*)(outp + 4) = make_float4(acc[i][4], acc[i][5], acc[i][6], acc[i][7]);
    }
}

// ---------------- bias + reshape + squash -> caps[B,1152,8] ----------------
__global__ void squash_caps_kernel(const float* __restrict__ pcb) {
    int idx = blockIdx.x * blockDim.x + threadIdx.x;  // b*1152 + i
    if (idx >= BATCH * NCAPS) return;
    int b = idx / NCAPS, i = idx % NCAPS;
    float v[8];
    float mag = 0.f;
#pragma unroll
    for (int k = 0; k < 8; k++) {
        int f = i * 8 + k;
        int oc = f / NPOS, p = f % NPOS;
        float t = g_c2[(size_t)oc * NDIM + b * NPOS + p] + pcb[oc];
        v[k] = t;
        mag += t * t;
    }
    float scale = mag / ((1.f + mag) * sqrtf(mag));
#pragma unroll
    for (int k = 0; k < 8; k++) g_caps[(size_t)idx * 8 + k] = v[k] * scale;
}

// ---------------- u_hat[b,i,j,d] = sum_k W[i,j,d,k]*caps[b,i,k] ----------------
__global__ void uhat_kernel(const float* __restrict__ W) {
    int i = blockIdx.x;            // 1152 blocks
    __shared__ float Ws[160 * 8];
    int t = threadIdx.x;           // 160 threads: t = j*16+d
    for (int q = t; q < 1280; q += 160) Ws[q] = W[(size_t)i * 1280 + q];
    __syncthreads();
    float wr[8];
#pragma unroll
    for (int k = 0; k < 8; k++) wr[k] = Ws[t * 8 + k];
    for (int b = 0; b < BATCH; b++) {
        const float* cp = g_caps + ((size_t)b * NCAPS + i) * 8;
        float acc = 0.f;
#pragma unroll
        for (int k = 0; k < 8; k++) acc += wr[k] * __ldg(cp + k);
        g_uhat[((size_t)b * NCAPS + i) * 160 + t] = acc;
    }
}

// ---------------- fused dynamic routing (3 iters), 1 block per batch ----------------
__global__ void routing_kernel(const float* __restrict__ dc_bias,
                               float* __restrict__ out) {
    extern __shared__ float sm[];
    float* bs = sm;             // [1152*10]
    float* cs = sm + 11520;     // [1152*10]
    float* sv = sm + 23040;     // [160] : s_j then v_j

    int b = blockIdx.x;
    int tid = threadIdx.x;      // 320 threads = 10 warps
    const float* U = g_uhat + (size_t)b * (NCAPS * 160);

    for (int q = tid; q < 11520; q += 320) bs[q] = 0.f;

    for (int r = 0; r < 3; r++) {
        __syncthreads();
        // softmax over j for each row i
        for (int i = tid; i < NCAPS; i += 320) {
            float row[10];
            float mx = -1e30f;
#pragma unroll
            for (int j = 0; j < 10; j++) {
                row[j] = bs[i * 10 + j];
                mx = fmaxf(mx, row[j]);
            }
            float sum = 0.f;
#pragma unroll
            for (int j = 0; j < 10; j++) {
                row[j] = expf(row[j] - mx);
                sum += row[j];
            }
            float inv = 1.f / sum;
#pragma unroll
            for (int j = 0; j < 10; j++) cs[i * 10 + j] = row[j] * inv;
        }
        __syncthreads();
        // s_j[d] = sum_i c_ij * u_hat[i,j,d] ; warp w handles j=w
        {
            int w = tid / 32, lane = tid % 32;
            int d = lane & 15, half = lane >> 4;
            float acc = 0.f;
            for (int i = half; i < NCAPS; i += 2)
                acc += cs[i * 10 + w] * U[(i * 10 + w) * 16 + d];
            acc += __shfl_xor_sync(0xffffffff, acc, 16);
            if (half == 0) sv[w * 16 + d] = acc + dc_bias[w * 16 + d];
        }
        __syncthreads();
        // squash s_j -> v_j
        if (tid < 160) {
            float val = sv[tid];
            float sq = val * val;
#pragma unroll
            for (int o = 8; o > 0; o >>= 1)
                sq += __shfl_xor_sync(0xffffffff, sq, o);
            float scale = sq / ((1.f + sq) * sqrtf(sq));
            float v = val * scale;
            sv[tid] = v;
            if (r == 2) out[b * 160 + tid] = v;
        }
        __syncthreads();
        // b_ij += <u_hat, v_j>
        if (r < 2) {
            for (int q = tid; q < 11520; q += 320) {
                const float* up = U + (size_t)q * 16;
                const float* vp = sv + (q % 10) * 16;
                float dot = 0.f;
#pragma unroll
                for (int dd = 0; dd < 16; dd++) dot += up[dd] * vp[dd];
                bs[q] += dot;
            }
        }
    }
}

// ---------------- launch ----------------
extern "C" void kernel_launch(void* const* d_in, const int* in_sizes, int n_in,
                              void* d_out, int out_size) {
    const float* x       = (const float*)d_in[0];  // [256,1,28,28]
    const float* conv1_w = (const float*)d_in[1];  // [256,1,9,9]
    const float* conv1_b = (const float*)d_in[2];  // [256]
    const float* pc_w    = (const float*)d_in[3];  // [256,256,9,9]
    const float* pc_b    = (const float*)d_in[4];  // [256]
    const float* W       = (const float*)d_in[5];  // [1152,10,16,8]
    const float* dc_bias = (const float*)d_in[6];  // [10,16]
    float* out = (float*)d_out;                    // [256,10,16]

    // conv1
    conv1_kernel<<<BATCH, 400>>>(x, conv1_w, conv1_b);

    // im2col
    {
        size_t total = (size_t)KDIM * NDIM;
        int threads = 256;
        int blocks = (int)((total + threads - 1) / threads);
        im2col_kernel<<<blocks, threads>>>();
    }

    // gemm (conv2)
    {
        dim3 grid(NDIM / BN, MDIM / BM);
        sgemm_kernel<<<grid, 256>>>(pc_w);
    }

    // squash -> caps
    {
        int total = BATCH * NCAPS;
        squash_caps_kernel<<<(total + 255) / 256, 256>>>(pc_b);
    }

    // u_hat
    uhat_kernel<<<NCAPS, 160>>>(W);

    // routing (needs >48KB dynamic smem)
    {
        size_t smem = (size_t)(23040 + 160) * sizeof(float);  // ~92.8KB
        static bool attr_set = false;
        cudaFuncSetAttribute(routing_kernel,
                             cudaFuncAttributeMaxDynamicSharedMemorySize,
                             (int)smem);
        (void)attr_set;
        routing_kernel<<<BATCH, 320, smem>>>(dc_bias, out);
    }
}

// round 3
// speedup vs baseline: 2.5500x; 2.5500x over previous
#include <cuda_runtime.h>
#include <cuda_bf16.h>
#include <cstdint>
#include <cstddef>

// ---------------- problem constants ----------------
#define BATCH 256
#define C1 256
#define H1 20
#define KDIM 20736        // 256*81
#define NDIM 9216         // 256*36
#define MDIM 256
#define NPOS 36
#define NCAPS 1152
#define VIN 8
#define NOUT 10
#define VOUT 16

// ---------------- scratch (device globals; allocation-free) ----------------
__device__ float g_h[(size_t)BATCH * C1 * H1 * H1];            // conv1 out
__device__ __nv_bfloat16 g_Ahi[(size_t)MDIM * KDIM];
__device__ __nv_bfloat16 g_Alo[(size_t)MDIM * KDIM];
__device__ __nv_bfloat16 g_Bhi[(size_t)NDIM * KDIM];           // im2col hi (K-major rows)
__device__ __nv_bfloat16 g_Blo[(size_t)NDIM * KDIM];
__device__ float g_c2[(size_t)MDIM * NDIM];
__device__ float g_caps[(size_t)BATCH * NCAPS * VIN];
__device__ float g_uhat[(size_t)BATCH * NCAPS * NOUT * VOUT];

// =================== PTX helpers (sm_80-compatible) ===================
__device__ __forceinline__ uint32_t smem_u32(const void* p) {
    uint32_t a;
    asm("{ .reg .u64 t; cvta.to.shared.u64 t, %1; cvt.u32.u64 %0, t; }"
        : "=r"(a) : "l"(p));
    return a;
}
__device__ __forceinline__ void cp_async16(uint32_t dst, const void* src) {
    asm volatile("cp.async.cg.shared.global [%0], [%1], 16;" :: "r"(dst), "l"(src));
}
#define CP_COMMIT() asm volatile("cp.async.commit_group;" ::: "memory")
#define CP_WAIT1()  asm volatile("cp.async.wait_group 1;" ::: "memory")
#define CP_WAIT0()  asm volatile("cp.async.wait_group 0;" ::: "memory")

__device__ __forceinline__ void ldsm_x4(uint32_t* r, uint32_t addr) {
    asm volatile("ldmatrix.sync.aligned.m8n8.x4.shared.b16 {%0,%1,%2,%3}, [%4];"
                 : "=r"(r[0]), "=r"(r[1]), "=r"(r[2]), "=r"(r[3]) : "r"(addr));
}
__device__ __forceinline__ void mma_bf16(float* d, const uint32_t* a, const uint32_t* b) {
    asm volatile(
        "mma.sync.aligned.m16n8k16.row.col.f32.bf16.bf16.f32 "
        "{%0,%1,%2,%3}, {%4,%5,%6,%7}, {%8,%9}, {%0,%1,%2,%3};"
        : "+f"(d[0]), "+f"(d[1]), "+f"(d[2]), "+f"(d[3])
        : "r"(a[0]), "r"(a[1]), "r"(a[2]), "r"(a[3]), "r"(b[0]), "r"(b[1]));
}

// ---------------- conv1: [B,1,28,28] -> [B,256,20,20] ----------------
__global__ void conv1_kernel(const float* __restrict__ x,
                             const float* __restrict__ w,
                             const float* __restrict__ bias) {
    int b = blockIdx.x;
    __shared__ float img[28 * 28];
    __shared__ float ws[8 * 81];
    int tid = threadIdx.x;  // 400 threads
    for (int i = tid; i < 784; i += 400) img[i] = x[(size_t)b * 784 + i];
    int y = tid / 20, xx = tid % 20;
    for (int oc0 = 0; oc0 < C1; oc0 += 8) {
        __syncthreads();
        for (int i = tid; i < 8 * 81; i += 400) ws[i] = w[oc0 * 81 + i];
        __syncthreads();
        float acc[8];
#pragma unroll
        for (int o = 0; o < 8; o++) acc[o] = bias[oc0 + o];
#pragma unroll
        for (int r = 0; r < 9; r++) {
#pragma unroll
            for (int s = 0; s < 9; s++) {
                float iv = img[(y + r) * 28 + xx + s];
                int k = r * 9 + s;
#pragma unroll
                for (int o = 0; o < 8; o++) acc[o] += iv * ws[o * 81 + k];
            }
        }
#pragma unroll
        for (int o = 0; o < 8; o++)
            g_h[((size_t)b * C1 + oc0 + o) * 400 + tid] = acc[o];
    }
}

// ---------------- convert A (pc_w) to bf16 hi/lo ----------------
__global__ void convertA_kernel(const float* __restrict__ pc_w) {
    int idx = blockIdx.x * blockDim.x + threadIdx.x;
    if (idx >= MDIM * KDIM) return;
    float v = pc_w[idx];
    __nv_bfloat16 hi = __float2bfloat16_rn(v);
    float lo = v - __bfloat162float(hi);
    g_Ahi[idx] = hi;
    g_Alo[idx] = __float2bfloat16_rn(lo);
}

// ---------------- im2col + convert B: rows n=[9216], cols k=[20736] ----------------
__global__ void im2colB_kernel() {
    int n = blockIdx.y;
    int k = blockIdx.x * 256 + threadIdx.x;
    int ic = k / 81;
    int rs = k - ic * 81;
    int r = rs / 9, s = rs - r * 9;
    int b = n / NPOS;
    int p = n - b * NPOS;
    int py = p / 6, px = p - py * 6;
    float v = g_h[(((size_t)b * C1 + ic) * H1 + 2 * py + r) * H1 + (2 * px + s)];
    __nv_bfloat16 hi = __float2bfloat16_rn(v);
    float lo = v - __bfloat162float(hi);
    size_t idx = (size_t)n * KDIM + k;
    g_Bhi[idx] = hi;
    g_Blo[idx] = __float2bfloat16_rn(lo);
}

// ---------------- HMMA GEMM: C[256,9216] = A[256,K] * B[9216,K]^T ----------------
// CTA tile 128x128, K-chunk 32, double-buffered cp.async, 8 warps (2x4), warp 64x32.
// 3-pass bf16 split: hi*hi + hi*lo + lo*hi.
#define GK 32
#define KITERS (KDIM / GK)       // 648
#define PITCH 80                 // bytes per smem row (32 bf16 + 16B pad) -> conflict-free
#define ARR_BYTES (128 * PITCH)  // 10240
#define STAGE_BYTES (4 * ARR_BYTES)  // 40960

__global__ __launch_bounds__(256, 1) void gemm_mma_kernel() {
    extern __shared__ char smem[];
    uint32_t sb = smem_u32(smem);
    int tid = threadIdx.x;
    int wid = tid >> 5, lane = tid & 31;
    int n0 = blockIdx.x * 128;
    int m0 = blockIdx.y * 128;
    int wm = wid >> 2;            // 0..1  (m offset 64*wm)
    int wn = wid & 3;             // 0..3  (n offset 32*wn)

    const __nv_bfloat16* srcs[4] = {
        g_Ahi + (size_t)m0 * KDIM, g_Alo + (size_t)m0 * KDIM,
        g_Bhi + (size_t)n0 * KDIM, g_Blo + (size_t)n0 * KDIM};

    // per-thread load slots: 8 chunks of 16B per stage
    int r0 = tid >> 2, c0 = (tid & 3);  // chunk coords within array (row 0..63 half? no:)
    // chunk index q = tid + j*256, j=0..1 per array: rows 0..127, 4 chunks/row

    // prologue: issue stages 0 and 1
#pragma unroll
    for (int st = 0; st < 2; st++) {
        int k0 = st * GK;
        uint32_t dstage = sb + st * STAGE_BYTES;
#pragma unroll
        for (int arr = 0; arr < 4; arr++) {
#pragma unroll
            for (int j = 0; j < 2; j++) {
                int q = tid + j * 256;
                int r = q >> 2, c = q & 3;
                cp_async16(dstage + arr * ARR_BYTES + r * PITCH + c * 16,
                           srcs[arr] + (size_t)r * KDIM + k0 + c * 8);
            }
        }
        CP_COMMIT();
    }

    float acc[4][4][4];
#pragma unroll
    for (int i = 0; i < 4; i++)
#pragma unroll
        for (int j = 0; j < 4; j++)
#pragma unroll
            for (int v = 0; v < 4; v++) acc[i][j][v] = 0.f;

    // fragment base addresses (lane-dependent)
    int aRow = wm * 64 + (lane & 15);
    int aColB = (lane >> 4) * 16;       // bytes: +8 halves for hi lane-group
    int bGroup = lane >> 3;             // 0..3
    int bWithin = lane & 7;
    int bRowOff = wn * 32 + ((bGroup >> 1) << 3) + bWithin;  // + j*8 per pair
    int bColB = (bGroup & 1) * 16;

    for (int it = 0; it < KITERS; it++) {
        CP_WAIT1();
        __syncthreads();
        uint32_t stage = sb + (it & 1) * STAGE_BYTES;

        uint32_t ahi[4][4], alo[4][4], bhi[4][2], blo[4][2];
#pragma unroll
        for (int ks = 0; ks < 2; ks++) {
            uint32_t kOffB = ks * 32;
            // A frags
#pragma unroll
            for (int mf = 0; mf < 4; mf++) {
                uint32_t adr = stage + (aRow + mf * 16) * PITCH + aColB + kOffB;
                ldsm_x4(ahi[mf], adr);                       // Ahi @ arr0
                ldsm_x4(alo[mf], adr + ARR_BYTES);           // Alo @ arr1
            }
            // B frags (pairs)
#pragma unroll
            for (int jp = 0; jp < 2; jp++) {
                uint32_t tmp[4];
                uint32_t adr = stage + 2 * ARR_BYTES +
                               (bRowOff + jp * 16) * PITCH + bColB + kOffB;
                ldsm_x4(tmp, adr);
                bhi[jp * 2 + 0][0] = tmp[0]; bhi[jp * 2 + 0][1] = tmp[1];
                bhi[jp * 2 + 1][0] = tmp[2]; bhi[jp * 2 + 1][1] = tmp[3];
                ldsm_x4(tmp, adr + ARR_BYTES);
                blo[jp * 2 + 0][0] = tmp[0]; blo[jp * 2 + 0][1] = tmp[1];
                blo[jp * 2 + 1][0] = tmp[2]; blo[jp * 2 + 1][1] = tmp[3];
            }
            // 3 passes
#pragma unroll
            for (int mf = 0; mf < 4; mf++)
#pragma unroll
                for (int nf = 0; nf < 4; nf++)
                    mma_bf16(acc[mf][nf], ahi[mf], bhi[nf]);
#pragma unroll
            for (int mf = 0; mf < 4; mf++)
#pragma unroll
                for (int nf = 0; nf < 4; nf++)
                    mma_bf16(acc[mf][nf], ahi[mf], blo[nf]);
#pragma unroll
            for (int mf = 0; mf < 4; mf++)
#pragma unroll
                for (int nf = 0; nf < 4; nf++)
                    mma_bf16(acc[mf][nf], alo[mf], bhi[nf]);
        }
        __syncthreads();
        // issue stage it+2 into the buffer just consumed
        if (it + 2 < KITERS) {
            int k0 = (it + 2) * GK;
            uint32_t dstage = sb + (it & 1) * STAGE_BYTES;
#pragma unroll
            for (int arr = 0; arr < 4; arr++) {
#pragma unroll
                for (int j = 0; j < 2; j++) {
                    int q = tid + j * 256;
                    int r = q >> 2, c = q & 3;
                    cp_async16(dstage + arr * ARR_BYTES + r * PITCH + c * 16,
                               srcs[arr] + (size_t)r * KDIM + k0 + c * 8);
                }
            }
        }
        CP_COMMIT();
    }

    // epilogue: direct global stores
    int g = lane >> 2, t = lane & 3;
#pragma unroll
    for (int mf = 0; mf < 4; mf++) {
#pragma unroll
        for (int nf = 0; nf < 4; nf++) {
            int m = m0 + wm * 64 + mf * 16 + g;
            int n = n0 + wn * 32 + nf * 8 + t * 2;
            float* p0 = g_c2 + (size_t)m * NDIM + n;
            float* p1 = g_c2 + (size_t)(m + 8) * NDIM + n;
            *(float2*)p0 = make_float2(acc[mf][nf][0], acc[mf][nf][1]);
            *(float2*)p1 = make_float2(acc[mf][nf][2], acc[mf][nf][3]);
        }
    }
}

// ---------------- bias + reshape + squash -> caps[B,1152,8] ----------------
__global__ void squash_caps_kernel(const float* __restrict__ pcb) {
    int idx = blockIdx.x * blockDim.x + threadIdx.x;
    if (idx >= BATCH * NCAPS) return;
    int b = idx / NCAPS, i = idx % NCAPS;
    float v[8];
    float mag = 0.f;
#pragma unroll
    for (int k = 0; k < 8; k++) {
        int f = i * 8 + k;
        int oc = f / NPOS, p = f % NPOS;
        float t = g_c2[(size_t)oc * NDIM + b * NPOS + p] + pcb[oc];
        v[k] = t;
        mag += t * t;
    }
    float scale = mag / ((1.f + mag) * sqrtf(mag));
#pragma unroll
    for (int k = 0; k < 8; k++) g_caps[(size_t)idx * 8 + k] = v[k] * scale;
}

// ---------------- u_hat[b,i,j,d] = sum_k W[i,j,d,k]*caps[b,i,k] ----------------
__global__ void uhat_kernel(const float* __restrict__ W) {
    int i = blockIdx.x;
    __shared__ float Ws[160 * 8];
    int t = threadIdx.x;  // 160 threads
    for (int q = t; q < 1280; q += 160) Ws[q] = W[(size_t)i * 1280 + q];
    __syncthreads();
    float wr[8];
#pragma unroll
    for (int k = 0; k < 8; k++) wr[k] = Ws[t * 8 + k];
    for (int b = 0; b < BATCH; b++) {
        const float* cp = g_caps + ((size_t)b * NCAPS + i) * 8;
        float acc = 0.f;
#pragma unroll
        for (int k = 0; k < 8; k++) acc += wr[k] * __ldg(cp + k);
        g_uhat[((size_t)b * NCAPS + i) * 160 + t] = acc;
    }
}

// ---------------- fused dynamic routing (3 iters), 1 block per batch ----------------
__global__ void routing_kernel(const float* __restrict__ dc_bias,
                               float* __restrict__ out) {
    extern __shared__ float sm[];
    float* bs = sm;
    float* cs = sm + 11520;
    float* sv = sm + 23040;

    int b = blockIdx.x;
    int tid = threadIdx.x;  // 320 threads
    const float* U = g_uhat + (size_t)b * (NCAPS * 160);

    for (int q = tid; q < 11520; q += 320) bs[q] = 0.f;

    for (int r = 0; r < 3; r++) {
        __syncthreads();
        for (int i = tid; i < NCAPS; i += 320) {
            float row[10];
            float mx = -1e30f;
#pragma unroll
            for (int j = 0; j < 10; j++) {
                row[j] = bs[i * 10 + j];
                mx = fmaxf(mx, row[j]);
            }
            float sum = 0.f;
#pragma unroll
            for (int j = 0; j < 10; j++) {
                row[j] = expf(row[j] - mx);
                sum += row[j];
            }
            float inv = 1.f / sum;
#pragma unroll
            for (int j = 0; j < 10; j++) cs[i * 10 + j] = row[j] * inv;
        }
        __syncthreads();
        {
            int w = tid / 32, lane = tid % 32;
            int d = lane & 15, half = lane >> 4;
            float acc = 0.f;
            for (int i = half; i < NCAPS; i += 2)
                acc += cs[i * 10 + w] * U[(i * 10 + w) * 16 + d];
            acc += __shfl_xor_sync(0xffffffff, acc, 16);
            if (half == 0) sv[w * 16 + d] = acc + dc_bias[w * 16 + d];
        }
        __syncthreads();
        if (tid < 160) {
            float val = sv[tid];
            float sq = val * val;
#pragma unroll
            for (int o = 8; o > 0; o >>= 1)
                sq += __shfl_xor_sync(0xffffffff, sq, o);
            float scale = sq / ((1.f + sq) * sqrtf(sq));
            float v = val * scale;
            sv[tid] = v;
            if (r == 2) out[b * 160 + tid] = v;
        }
        __syncthreads();
        if (r < 2) {
            for (int q = tid; q < 11520; q += 320) {
                const float* up = U + (size_t)q * 16;
                const float* vp = sv + (q % 10) * 16;
                float dot = 0.f;
#pragma unroll
                for (int dd = 0; dd < 16; dd++) dot += up[dd] * vp[dd];
                bs[q] += dot;
            }
        }
    }
}

// ---------------- launch ----------------
extern "C" void kernel_launch(void* const* d_in, const int* in_sizes, int n_in,
                              void* d_out, int out_size) {
    const float* x       = (const float*)d_in[0];
    const float* conv1_w = (const float*)d_in[1];
    const float* conv1_b = (const float*)d_in[2];
    const float* pc_w    = (const float*)d_in[3];
    const float* pc_b    = (const float*)d_in[4];
    const float* W       = (const float*)d_in[5];
    const float* dc_bias = (const float*)d_in[6];
    float* out = (float*)d_out;

    conv1_kernel<<<BATCH, 400>>>(x, conv1_w, conv1_b);

    {
        int total = MDIM * KDIM;
        convertA_kernel<<<(total + 255) / 256, 256>>>(pc_w);
    }

    {
        dim3 grid(KDIM / 256, NDIM);
        im2colB_kernel<<<grid, 256>>>();
    }

    {
        size_t smem = 2 * STAGE_BYTES;  // 81920
        cudaFuncSetAttribute(gemm_mma_kernel,
                             cudaFuncAttributeMaxDynamicSharedMemorySize, (int)smem);
        dim3 grid(NDIM / 128, MDIM / 128);
        gemm_mma_kernel<<<grid, 256, smem>>>();
    }

    {
        int total = BATCH * NCAPS;
        squash_caps_kernel<<<(total + 255) / 256, 256>>>(pc_b);
    }

    uhat_kernel<<<NCAPS, 160>>>(W);

    {
        size_t smem = (size_t)(23040 + 160) * sizeof(float);
        cudaFuncSetAttribute(routing_kernel,
                             cudaFuncAttributeMaxDynamicSharedMemorySize, (int)smem);
        routing_kernel<<<BATCH, 320, smem>>>(dc_bias, out);
    }
}

// round 4
// speedup vs baseline: 2.9470x; 1.1557x over previous
#include <cuda_runtime.h>
#include <cuda_bf16.h>
#include <cstdint>
#include <cstddef>

// ---------------- problem constants ----------------
#define BATCH 256
#define C1 256
#define H1 20
#define KDIM 20736        // 256*81
#define NDIM 9216         // 256*36
#define MDIM 256
#define NPOS 36
#define NCAPS 1152
#define VIN 8
#define NOUT 10
#define VOUT 16

// ---------------- scratch (device globals; allocation-free) ----------------
__device__ float g_h[(size_t)BATCH * C1 * 400];                // conv1 out
__device__ __nv_bfloat16 g_Ahi[(size_t)MDIM * KDIM];
__device__ __nv_bfloat16 g_Alo[(size_t)MDIM * KDIM];
__device__ __nv_bfloat16 g_Bhi[(size_t)NDIM * KDIM];           // im2col hi (K-major rows)
__device__ __nv_bfloat16 g_Blo[(size_t)NDIM * KDIM];
__device__ float g_c2[(size_t)MDIM * NDIM];
__device__ float g_caps[(size_t)BATCH * NCAPS * VIN];
__device__ float g_uhat[(size_t)BATCH * NCAPS * NOUT * VOUT];

// =================== PTX helpers ===================
__device__ __forceinline__ uint32_t smem_u32(const void* p) {
    uint32_t a;
    asm("{ .reg .u64 t; cvta.to.shared.u64 t, %1; cvt.u32.u64 %0, t; }"
        : "=r"(a) : "l"(p));
    return a;
}
__device__ __forceinline__ void cp_async16(uint32_t dst, const void* src) {
    asm volatile("cp.async.cg.shared.global [%0], [%1], 16;" :: "r"(dst), "l"(src));
}
#define CP_COMMIT() asm volatile("cp.async.commit_group;" ::: "memory")
#define CP_WAIT1()  asm volatile("cp.async.wait_group 1;" ::: "memory")

__device__ __forceinline__ void ldsm_x4(uint32_t* r, uint32_t addr) {
    asm volatile("ldmatrix.sync.aligned.m8n8.x4.shared.b16 {%0,%1,%2,%3}, [%4];"
                 : "=r"(r[0]), "=r"(r[1]), "=r"(r[2]), "=r"(r[3]) : "r"(addr));
}
__device__ __forceinline__ void mma_bf16(float* d, const uint32_t* a, const uint32_t* b) {
    asm volatile(
        "mma.sync.aligned.m16n8k16.row.col.f32.bf16.bf16.f32 "
        "{%0,%1,%2,%3}, {%4,%5,%6,%7}, {%8,%9}, {%0,%1,%2,%3};"
        : "+f"(d[0]), "+f"(d[1]), "+f"(d[2]), "+f"(d[3])
        : "r"(a[0]), "r"(a[1]), "r"(a[2]), "r"(a[3]), "r"(b[0]), "r"(b[1]));
}

// ---------------- conv1 (GEMM-style): [B,1,28,28] -> [B,256,20,20] ----------------
// grid (10, 256): blockIdx.x = octile*5 + postile? -> encode: x = oc2*5 + pos5
// block 256 threads (16 tx pos-groups x 16 ty oc-groups); micro-tile 8 oc x 5 pos.
__global__ __launch_bounds__(256) void conv1_kernel(const float* __restrict__ x,
                                                    const float* __restrict__ w,
                                                    const float* __restrict__ bias) {
    __shared__ float img[784];
    __shared__ float ws[81 * 128];
    int b = blockIdx.y;
    int oct = (blockIdx.x / 5) * 128;
    int pt = (blockIdx.x % 5) * 80;
    int tid = threadIdx.x;
    int tx = tid & 15, ty = tid >> 4;

    for (int i = tid; i < 784; i += 256) img[i] = x[(size_t)b * 784 + i];
    for (int idx = tid; idx < 81 * 128; idx += 256) {
        int o = idx / 81, k = idx - o * 81;
        ws[k * 128 + o] = w[(size_t)(oct + o) * 81 + k];
    }
    __syncthreads();

    int ibase[5];
#pragma unroll
    for (int q = 0; q < 5; q++) {
        int pos = pt + q * 16 + tx;
        int py = pos / 20, px = pos - py * 20;
        ibase[q] = py * 28 + px;
    }
    float acc[8][5];
#pragma unroll
    for (int o = 0; o < 8; o++) {
        float bv = bias[oct + ty * 8 + o];
#pragma unroll
        for (int q = 0; q < 5; q++) acc[o][q] = bv;
    }
#pragma unroll
    for (int r = 0; r < 9; r++) {
#pragma unroll
        for (int s = 0; s < 9; s++) {
            int k = r * 9 + s;
            int off = r * 28 + s;
            float iv[5];
#pragma unroll
            for (int q = 0; q < 5; q++) iv[q] = img[ibase[q] + off];
            float4 a0 = *(const float4*)&ws[k * 128 + ty * 8];
            float4 a1 = *(const float4*)&ws[k * 128 + ty * 8 + 4];
            float af[8] = {a0.x, a0.y, a0.z, a0.w, a1.x, a1.y, a1.z, a1.w};
#pragma unroll
            for (int o = 0; o < 8; o++)
#pragma unroll
                for (int q = 0; q < 5; q++) acc[o][q] += af[o] * iv[q];
        }
    }
#pragma unroll
    for (int o = 0; o < 8; o++) {
        int oc = oct + ty * 8 + o;
        float* dst = g_h + ((size_t)b * C1 + oc) * 400 + pt + tx;
#pragma unroll
        for (int q = 0; q < 5; q++) dst[q * 16] = acc[o][q];
    }
}

// ---------------- convert A (pc_w) to bf16 hi/lo ----------------
__global__ void convertA_kernel(const float* __restrict__ pc_w) {
    int idx = blockIdx.x * blockDim.x + threadIdx.x;
    if (idx >= MDIM * KDIM) return;
    float v = pc_w[idx];
    __nv_bfloat16 hi = __float2bfloat16_rn(v);
    float lo = v - __bfloat162float(hi);
    g_Ahi[idx] = hi;
    g_Alo[idx] = __float2bfloat16_rn(lo);
}

// ---------------- im2col + convert B ----------------
__global__ void im2colB_kernel() {
    int n = blockIdx.y;
    int k = blockIdx.x * 256 + threadIdx.x;
    int ic = k / 81;
    int rs = k - ic * 81;
    int r = rs / 9, s = rs - r * 9;
    int b = n / NPOS;
    int p = n - b * NPOS;
    int py = p / 6, px = p - py * 6;
    float v = g_h[((size_t)b * C1 + ic) * 400 + (2 * py + r) * H1 + (2 * px + s)];
    __nv_bfloat16 hi = __float2bfloat16_rn(v);
    float lo = v - __bfloat162float(hi);
    size_t idx = (size_t)n * KDIM + k;
    g_Bhi[idx] = hi;
    g_Blo[idx] = __float2bfloat16_rn(lo);
}

// ---------------- HMMA GEMM: C[256,9216] = A[256,K] * B[9216,K]^T ----------------
// CTA 128x128, K-chunk 64, 3-stage cp.async pipeline, 8 warps (2x4), warp 64x32.
#define GK 64
#define KITERS (KDIM / GK)           // 324
#define PITCH 144                    // 128B data + 16B pad -> conflict-free ldmatrix
#define ARR_BYTES (128 * PITCH)      // 18432
#define STAGE_BYTES (4 * ARR_BYTES)  // 73728
#define NSTAGE 3

__global__ __launch_bounds__(256, 1) void gemm_mma_kernel() {
    extern __shared__ char smem[];
    uint32_t sb = smem_u32(smem);
    int tid = threadIdx.x;
    int wid = tid >> 5, lane = tid & 31;
    int n0 = blockIdx.x * 128;
    int m0 = blockIdx.y * 128;
    int wm = wid >> 2;
    int wn = wid & 3;

    const __nv_bfloat16* srcs[4] = {
        g_Ahi + (size_t)m0 * KDIM, g_Alo + (size_t)m0 * KDIM,
        g_Bhi + (size_t)n0 * KDIM, g_Blo + (size_t)n0 * KDIM};

    // prologue: stages 0,1
#pragma unroll
    for (int st = 0; st < 2; st++) {
        int k0 = st * GK;
        uint32_t dstage = sb + st * STAGE_BYTES;
#pragma unroll
        for (int arr = 0; arr < 4; arr++) {
#pragma unroll
            for (int j = 0; j < 4; j++) {
                int q = tid + j * 256;
                int r = q >> 3, c = q & 7;
                cp_async16(dstage + arr * ARR_BYTES + r * PITCH + c * 16,
                           srcs[arr] + (size_t)r * KDIM + k0 + c * 8);
            }
        }
        CP_COMMIT();
    }

    float acc[4][4][4];
#pragma unroll
    for (int i = 0; i < 4; i++)
#pragma unroll
        for (int j = 0; j < 4; j++)
#pragma unroll
            for (int v = 0; v < 4; v++) acc[i][j][v] = 0.f;

    int aRow = wm * 64 + (lane & 15);
    int aColB = (lane >> 4) * 16;
    int bGroup = lane >> 3;
    int bWithin = lane & 7;
    int bRowOff = wn * 32 + ((bGroup >> 1) << 3) + bWithin;
    int bColB = (bGroup & 1) * 16;

    for (int it = 0; it < KITERS; it++) {
        CP_WAIT1();
        __syncthreads();
        // prefetch stage it+2 (buffer (it+2)%3 was consumed at iter it-1)
        if (it + 2 < KITERS) {
            int k0 = (it + 2) * GK;
            uint32_t dstage = sb + ((it + 2) % NSTAGE) * STAGE_BYTES;
#pragma unroll
            for (int arr = 0; arr < 4; arr++) {
#pragma unroll
                for (int j = 0; j < 4; j++) {
                    int q = tid + j * 256;
                    int r = q >> 3, c = q & 7;
                    cp_async16(dstage + arr * ARR_BYTES + r * PITCH + c * 16,
                               srcs[arr] + (size_t)r * KDIM + k0 + c * 8);
                }
            }
        }
        CP_COMMIT();

        uint32_t stage = sb + (it % NSTAGE) * STAGE_BYTES;
#pragma unroll
        for (int ks = 0; ks < 4; ks++) {
            uint32_t kOffB = ks * 32;
            uint32_t ahi[4][4], alo[4][4], bhi[4][2], blo[4][2];
#pragma unroll
            for (int mf = 0; mf < 4; mf++) {
                uint32_t adr = stage + (aRow + mf * 16) * PITCH + aColB + kOffB;
                ldsm_x4(ahi[mf], adr);
                ldsm_x4(alo[mf], adr + ARR_BYTES);
            }
#pragma unroll
            for (int jp = 0; jp < 2; jp++) {
                uint32_t tmp[4];
                uint32_t adr = stage + 2 * ARR_BYTES +
                               (bRowOff + jp * 16) * PITCH + bColB + kOffB;
                ldsm_x4(tmp, adr);
                bhi[jp * 2 + 0][0] = tmp[0]; bhi[jp * 2 + 0][1] = tmp[1];
                bhi[jp * 2 + 1][0] = tmp[2]; bhi[jp * 2 + 1][1] = tmp[3];
                ldsm_x4(tmp, adr + ARR_BYTES);
                blo[jp * 2 + 0][0] = tmp[0]; blo[jp * 2 + 0][1] = tmp[1];
                blo[jp * 2 + 1][0] = tmp[2]; blo[jp * 2 + 1][1] = tmp[3];
            }
#pragma unroll
            for (int mf = 0; mf < 4; mf++)
#pragma unroll
                for (int nf = 0; nf < 4; nf++)
                    mma_bf16(acc[mf][nf], ahi[mf], bhi[nf]);
#pragma unroll
            for (int mf = 0; mf < 4; mf++)
#pragma unroll
                for (int nf = 0; nf < 4; nf++)
                    mma_bf16(acc[mf][nf], ahi[mf], blo[nf]);
#pragma unroll
            for (int mf = 0; mf < 4; mf++)
#pragma unroll
                for (int nf = 0; nf < 4; nf++)
                    mma_bf16(acc[mf][nf], alo[mf], bhi[nf]);
        }
    }

    int g = lane >> 2, t = lane & 3;
#pragma unroll
    for (int mf = 0; mf < 4; mf++) {
#pragma unroll
        for (int nf = 0; nf < 4; nf++) {
            int m = m0 + wm * 64 + mf * 16 + g;
            int n = n0 + wn * 32 + nf * 8 + t * 2;
            float* p0 = g_c2 + (size_t)m * NDIM + n;
            float* p1 = g_c2 + (size_t)(m + 8) * NDIM + n;
            *(float2*)p0 = make_float2(acc[mf][nf][0], acc[mf][nf][1]);
            *(float2*)p1 = make_float2(acc[mf][nf][2], acc[mf][nf][3]);
        }
    }
}

// ---------------- bias + reshape + squash -> caps[B,1152,8] ----------------
__global__ void squash_caps_kernel(const float* __restrict__ pcb) {
    int idx = blockIdx.x * blockDim.x + threadIdx.x;
    if (idx >= BATCH * NCAPS) return;
    int b = idx / NCAPS, i = idx % NCAPS;
    float v[8];
    float mag = 0.f;
#pragma unroll
    for (int k = 0; k < 8; k++) {
        int f = i * 8 + k;
        int oc = f / NPOS, p = f % NPOS;
        float t = g_c2[(size_t)oc * NDIM + b * NPOS + p] + pcb[oc];
        v[k] = t;
        mag += t * t;
    }
    float scale = mag / ((1.f + mag) * sqrtf(mag));
#pragma unroll
    for (int k = 0; k < 8; k++) g_caps[(size_t)idx * 8 + k] = v[k] * scale;
}

// ---------------- u_hat: grid (1152, 8), block 160 ----------------
__global__ void uhat_kernel(const float* __restrict__ W) {
    int i = blockIdx.x;
    int b0 = blockIdx.y * 32;
    __shared__ float Ws[160 * 8];
    int t = threadIdx.x;
    for (int q = t; q < 1280; q += 160) Ws[q] = W[(size_t)i * 1280 + q];
    __syncthreads();
    float wr[8];
#pragma unroll
    for (int k = 0; k < 8; k++) wr[k] = Ws[t * 8 + k];
    for (int b = b0; b < b0 + 32; b++) {
        const float* cp = g_caps + ((size_t)b * NCAPS + i) * 8;
        float acc = 0.f;
#pragma unroll
        for (int k = 0; k < 8; k++) acc += wr[k] * __ldg(cp + k);
        g_uhat[((size_t)b * NCAPS + i) * 160 + t] = acc;
    }
}

// ---------------- fused dynamic routing, warp-cooperative, 3 U-passes ----------------
// block per batch element, 256 threads = 8 warps. Lane l owns elements e=m*32+l
// of each 160-vector (j = 2m + (l>>4), d = l&15).
__global__ __launch_bounds__(256) void routing_kernel(const float* __restrict__ dc_bias,
                                                      float* __restrict__ out) {
    extern __shared__ float sm[];
    float* bs = sm;               // [1152*10]
    float* swarp = sm + 11520;    // [8*160]
    float* vsm = sm + 11520 + 1280;  // [160]

    int b = blockIdx.x;
    int tid = threadIdx.x;
    int wid = tid >> 5, lane = tid & 31;
    int half = lane >> 4;         // j parity
    const float* U = g_uhat + (size_t)b * (NCAPS * 160);

    for (int r = 0; r < 3; r++) {
        float vreg[5];
        if (r > 0) {
#pragma unroll
            for (int m = 0; m < 5; m++) vreg[m] = vsm[m * 32 + lane];
        }
        float sp[5] = {0.f, 0.f, 0.f, 0.f, 0.f};

        for (int i = wid; i < NCAPS; i += 8) {
            float u[5];
            const float* up = U + (size_t)i * 160;
#pragma unroll
            for (int m = 0; m < 5; m++) u[m] = up[m * 32 + lane];

            if (r == 0) {
#pragma unroll
                for (int m = 0; m < 5; m++) sp[m] += 0.1f * u[m];
                if ((lane & 15) == 0) {
#pragma unroll
                    for (int m = 0; m < 5; m++) bs[i * 10 + 2 * m + half] = 0.f;
                }
            } else {
                float bj[5];
#pragma unroll
                for (int m = 0; m < 5; m++) {
                    float t = u[m] * vreg[m];
                    t += __shfl_xor_sync(0xffffffff, t, 1);
                    t += __shfl_xor_sync(0xffffffff, t, 2);
                    t += __shfl_xor_sync(0xffffffff, t, 4);
                    t += __shfl_xor_sync(0xffffffff, t, 8);
                    bj[m] = bs[i * 10 + 2 * m + half] + t;
                }
                if (r == 1 && (lane & 15) == 0) {
#pragma unroll
                    for (int m = 0; m < 5; m++) bs[i * 10 + 2 * m + half] = bj[m];
                }
                float mx = bj[0];
#pragma unroll
                for (int m = 1; m < 5; m++) mx = fmaxf(mx, bj[m]);
                mx = fmaxf(mx, __shfl_xor_sync(0xffffffff, mx, 16));
                float es[5], ssum = 0.f;
#pragma unroll
                for (int m = 0; m < 5; m++) {
                    es[m] = expf(bj[m] - mx);
                    ssum += es[m];
                }
                ssum += __shfl_xor_sync(0xffffffff, ssum, 16);
                float inv = 1.f / ssum;
#pragma unroll
                for (int m = 0; m < 5; m++) sp[m] += (es[m] * inv) * u[m];
            }
        }
#pragma unroll
        for (int m = 0; m < 5; m++) swarp[wid * 160 + m * 32 + lane] = sp[m];
        __syncthreads();
        if (tid < 160) {
            float s = dc_bias[tid];
#pragma unroll
            for (int w = 0; w < 8; w++) s += swarp[w * 160 + tid];
            float sq = s * s;
#pragma unroll
            for (int o = 8; o > 0; o >>= 1)
                sq += __shfl_xor_sync(0xffffffff, sq, o);
            float scale = sq / ((1.f + sq) * sqrtf(sq));
            float v = s * scale;
            vsm[tid] = v;
            if (r == 2) out[b * 160 + tid] = v;
        }
        __syncthreads();
    }
}

// ---------------- launch ----------------
extern "C" void kernel_launch(void* const* d_in, const int* in_sizes, int n_in,
                              void* d_out, int out_size) {
    const float* x       = (const float*)d_in[0];
    const float* conv1_w = (const float*)d_in[1];
    const float* conv1_b = (const float*)d_in[2];
    const float* pc_w    = (const float*)d_in[3];
    const float* pc_b    = (const float*)d_in[4];
    const float* W       = (const float*)d_in[5];
    const float* dc_bias = (const float*)d_in[6];
    float* out = (float*)d_out;

    {
        dim3 grid(10, 256);
        conv1_kernel<<<grid, 256>>>(x, conv1_w, conv1_b);
    }

    {
        int total = MDIM * KDIM;
        convertA_kernel<<<(total + 255) / 256, 256>>>(pc_w);
    }

    {
        dim3 grid(KDIM / 256, NDIM);
        im2colB_kernel<<<grid, 256>>>();
    }

    {
        size_t smem = NSTAGE * STAGE_BYTES;  // 221184
        cudaFuncSetAttribute(gemm_mma_kernel,
                             cudaFuncAttributeMaxDynamicSharedMemorySize, (int)smem);
        dim3 grid(NDIM / 128, MDIM / 128);
        gemm_mma_kernel<<<grid, 256, smem>>>();
    }

    {
        int total = BATCH * NCAPS;
        squash_caps_kernel<<<(total + 255) / 256, 256>>>(pc_b);
    }

    {
        dim3 grid(NCAPS, 8);
        uhat_kernel<<<grid, 160>>>(W);
    }

    {
        size_t smem = (size_t)(11520 + 1280 + 160) * sizeof(float);  // 51840
        cudaFuncSetAttribute(routing_kernel,
                             cudaFuncAttributeMaxDynamicSharedMemorySize, (int)smem);
        routing_kernel<<<BATCH, 256, smem>>>(dc_bias, out);
    }
}

// round 5
// speedup vs baseline: 3.2407x; 1.0997x over previous
#include <cuda_runtime.h>
#include <cuda_bf16.h>
#include <cstdint>
#include <cstddef>

// ---------------- problem constants ----------------
#define BATCH 256
#define C1 256
#define H1 20
#define KDIM 20736        // 256*81
#define NDIM 9216         // 256*36
#define MDIM 256
#define NPOS 36
#define NCAPS 1152
#define VIN 8
#define NOUT 10
#define VOUT 16

// ---------------- scratch (device globals; allocation-free) ----------------
__device__ float g_h[(size_t)BATCH * C1 * 400];                // conv1 out
__device__ __nv_bfloat16 g_Ahi[(size_t)MDIM * KDIM];
__device__ __nv_bfloat16 g_Alo[(size_t)MDIM * KDIM];
__device__ __nv_bfloat16 g_Bhi[(size_t)NDIM * KDIM];           // im2col hi (K-major rows)
__device__ __nv_bfloat16 g_Blo[(size_t)NDIM * KDIM];
__device__ float g_c2[(size_t)MDIM * NDIM];
__device__ float g_caps[(size_t)BATCH * NCAPS * VIN];
__device__ float g_uhat[(size_t)BATCH * NCAPS * NOUT * VOUT];

// =================== PTX helpers ===================
__device__ __forceinline__ uint32_t smem_u32(const void* p) {
    uint32_t a;
    asm("{ .reg .u64 t; cvta.to.shared.u64 t, %1; cvt.u32.u64 %0, t; }"
        : "=r"(a) : "l"(p));
    return a;
}
__device__ __forceinline__ void cp_async16(uint32_t dst, const void* src) {
    asm volatile("cp.async.cg.shared.global [%0], [%1], 16;" :: "r"(dst), "l"(src));
}
#define CP_COMMIT() asm volatile("cp.async.commit_group;" ::: "memory")
#define CP_WAIT1()  asm volatile("cp.async.wait_group 1;" ::: "memory")

__device__ __forceinline__ void ldsm_x4(uint32_t* r, uint32_t addr) {
    asm volatile("ldmatrix.sync.aligned.m8n8.x4.shared.b16 {%0,%1,%2,%3}, [%4];"
                 : "=r"(r[0]), "=r"(r[1]), "=r"(r[2]), "=r"(r[3]) : "r"(addr));
}
__device__ __forceinline__ void mma_bf16(float* d, const uint32_t* a, const uint32_t* b) {
    asm volatile(
        "mma.sync.aligned.m16n8k16.row.col.f32.bf16.bf16.f32 "
        "{%0,%1,%2,%3}, {%4,%5,%6,%7}, {%8,%9}, {%0,%1,%2,%3};"
        : "+f"(d[0]), "+f"(d[1]), "+f"(d[2]), "+f"(d[3])
        : "r"(a[0]), "r"(a[1]), "r"(a[2]), "r"(a[3]), "r"(b[0]), "r"(b[1]));
}

// ---------------- conv1 (GEMM-style): [B,1,28,28] -> [B,256,20,20] ----------------
__global__ __launch_bounds__(256) void conv1_kernel(const float* __restrict__ x,
                                                    const float* __restrict__ w,
                                                    const float* __restrict__ bias) {
    __shared__ float img[784];
    __shared__ float ws[81 * 128];
    int b = blockIdx.y;
    int oct = (blockIdx.x / 5) * 128;
    int pt = (blockIdx.x % 5) * 80;
    int tid = threadIdx.x;
    int tx = tid & 15, ty = tid >> 4;

    for (int i = tid; i < 784; i += 256) img[i] = x[(size_t)b * 784 + i];
    for (int idx = tid; idx < 81 * 128; idx += 256) {
        int o = idx / 81, k = idx - o * 81;
        ws[k * 128 + o] = w[(size_t)(oct + o) * 81 + k];
    }
    __syncthreads();

    int ibase[5];
#pragma unroll
    for (int q = 0; q < 5; q++) {
        int pos = pt + q * 16 + tx;
        int py = pos / 20, px = pos - py * 20;
        ibase[q] = py * 28 + px;
    }
    float acc[8][5];
#pragma unroll
    for (int o = 0; o < 8; o++) {
        float bv = bias[oct + ty * 8 + o];
#pragma unroll
        for (int q = 0; q < 5; q++) acc[o][q] = bv;
    }
#pragma unroll
    for (int r = 0; r < 9; r++) {
#pragma unroll
        for (int s = 0; s < 9; s++) {
            int k = r * 9 + s;
            int off = r * 28 + s;
            float iv[5];
#pragma unroll
            for (int q = 0; q < 5; q++) iv[q] = img[ibase[q] + off];
            float4 a0 = *(const float4*)&ws[k * 128 + ty * 8];
            float4 a1 = *(const float4*)&ws[k * 128 + ty * 8 + 4];
            float af[8] = {a0.x, a0.y, a0.z, a0.w, a1.x, a1.y, a1.z, a1.w};
#pragma unroll
            for (int o = 0; o < 8; o++)
#pragma unroll
                for (int q = 0; q < 5; q++) acc[o][q] += af[o] * iv[q];
        }
    }
#pragma unroll
    for (int o = 0; o < 8; o++) {
        int oc = oct + ty * 8 + o;
        float* dst = g_h + ((size_t)b * C1 + oc) * 400 + pt + tx;
#pragma unroll
        for (int q = 0; q < 5; q++) dst[q * 16] = acc[o][q];
    }
}

// ---------------- convert A (pc_w) to bf16 hi/lo ----------------
__global__ void convertA_kernel(const float* __restrict__ pc_w) {
    int idx = blockIdx.x * blockDim.x + threadIdx.x;
    if (idx >= MDIM * KDIM) return;
    float v = pc_w[idx];
    __nv_bfloat16 hi = __float2bfloat16_rn(v);
    float lo = v - __bfloat162float(hi);
    g_Ahi[idx] = hi;
    g_Alo[idx] = __float2bfloat16_rn(lo);
}

// ---------------- im2col + convert B (2 k per thread, packed stores) ----------------
__global__ __launch_bounds__(128) void im2colB_kernel() {
    int n = blockIdx.y;
    int k0 = blockIdx.x * 256 + threadIdx.x * 2;
    int b = n / NPOS;
    int p = n - b * NPOS;
    int py = p / 6, px = p - py * 6;
    const float* hb = g_h + (size_t)b * C1 * 400 + (2 * py) * H1 + 2 * px;

    __nv_bfloat16 hi2[2], lo2[2];
#pragma unroll
    for (int e = 0; e < 2; e++) {
        int k = k0 + e;
        int ic = k / 81;
        int rs = k - ic * 81;
        int r = rs / 9, s = rs - r * 9;
        float v = hb[(size_t)ic * 400 + r * H1 + s];
        __nv_bfloat16 hi = __float2bfloat16_rn(v);
        hi2[e] = hi;
        lo2[e] = __float2bfloat16_rn(v - __bfloat162float(hi));
    }
    size_t idx2 = ((size_t)n * KDIM + k0) >> 1;
    ((__nv_bfloat162*)g_Bhi)[idx2] = __nv_bfloat162(hi2[0], hi2[1]);
    ((__nv_bfloat162*)g_Blo)[idx2] = __nv_bfloat162(lo2[0], lo2[1]);
}

// ---------------- HMMA GEMM: C[256,9216] = A[256,K] * B[9216,K]^T ----------------
// CTA 128x128, K-chunk 64, 3-stage cp.async pipeline, 16 warps (4x4), warp 32x32.
#define GK 64
#define KITERS (KDIM / GK)           // 324
#define PITCH 144                    // 128B data + 16B pad -> conflict-free ldmatrix
#define ARR_BYTES (128 * PITCH)      // 18432
#define STAGE_BYTES (4 * ARR_BYTES)  // 73728
#define NSTAGE 3

__global__ __launch_bounds__(512, 1) void gemm_mma_kernel() {
    extern __shared__ char smem[];
    uint32_t sb = smem_u32(smem);
    int tid = threadIdx.x;
    int wid = tid >> 5, lane = tid & 31;
    int n0 = blockIdx.x * 128;
    int m0 = blockIdx.y * 128;
    int wm = wid >> 2;            // 0..3, m offset 32*wm
    int wn = wid & 3;             // 0..3, n offset 32*wn

    const __nv_bfloat16* srcs[4] = {
        g_Ahi + (size_t)m0 * KDIM, g_Alo + (size_t)m0 * KDIM,
        g_Bhi + (size_t)n0 * KDIM, g_Blo + (size_t)n0 * KDIM};

    // prologue: stages 0,1  (1024 chunks/array, 2 per thread)
#pragma unroll
    for (int st = 0; st < 2; st++) {
        int k0 = st * GK;
        uint32_t dstage = sb + st * STAGE_BYTES;
#pragma unroll
        for (int arr = 0; arr < 4; arr++) {
#pragma unroll
            for (int j = 0; j < 2; j++) {
                int q = tid + j * 512;
                int r = q >> 3, c = q & 7;
                cp_async16(dstage + arr * ARR_BYTES + r * PITCH + c * 16,
                           srcs[arr] + (size_t)r * KDIM + k0 + c * 8);
            }
        }
        CP_COMMIT();
    }

    float acc[2][4][4];
#pragma unroll
    for (int i = 0; i < 2; i++)
#pragma unroll
        for (int j = 0; j < 4; j++)
#pragma unroll
            for (int v = 0; v < 4; v++) acc[i][j][v] = 0.f;

    int aRow = wm * 32 + (lane & 15);
    int aColB = (lane >> 4) * 16;
    int bGroup = lane >> 3;
    int bWithin = lane & 7;
    int bRowOff = wn * 32 + ((bGroup >> 1) << 3) + bWithin;
    int bColB = (bGroup & 1) * 16;

    for (int it = 0; it < KITERS; it++) {
        CP_WAIT1();
        __syncthreads();
        if (it + 2 < KITERS) {
            int k0 = (it + 2) * GK;
            uint32_t dstage = sb + ((it + 2) % NSTAGE) * STAGE_BYTES;
#pragma unroll
            for (int arr = 0; arr < 4; arr++) {
#pragma unroll
                for (int j = 0; j < 2; j++) {
                    int q = tid + j * 512;
                    int r = q >> 3, c = q & 7;
                    cp_async16(dstage + arr * ARR_BYTES + r * PITCH + c * 16,
                               srcs[arr] + (size_t)r * KDIM + k0 + c * 8);
                }
            }
        }
        CP_COMMIT();

        uint32_t stage = sb + (it % NSTAGE) * STAGE_BYTES;
#pragma unroll
        for (int ks = 0; ks < 4; ks++) {
            uint32_t kOffB = ks * 32;
            uint32_t ahi[2][4], alo[2][4], bhi[4][2], blo[4][2];
#pragma unroll
            for (int mf = 0; mf < 2; mf++) {
                uint32_t adr = stage + (aRow + mf * 16) * PITCH + aColB + kOffB;
                ldsm_x4(ahi[mf], adr);
                ldsm_x4(alo[mf], adr + ARR_BYTES);
            }
#pragma unroll
            for (int jp = 0; jp < 2; jp++) {
                uint32_t tmp[4];
                uint32_t adr = stage + 2 * ARR_BYTES +
                               (bRowOff + jp * 16) * PITCH + bColB + kOffB;
                ldsm_x4(tmp, adr);
                bhi[jp * 2 + 0][0] = tmp[0]; bhi[jp * 2 + 0][1] = tmp[1];
                bhi[jp * 2 + 1][0] = tmp[2]; bhi[jp * 2 + 1][1] = tmp[3];
                ldsm_x4(tmp, adr + ARR_BYTES);
                blo[jp * 2 + 0][0] = tmp[0]; blo[jp * 2 + 0][1] = tmp[1];
                blo[jp * 2 + 1][0] = tmp[2]; blo[jp * 2 + 1][1] = tmp[3];
            }
#pragma unroll
            for (int mf = 0; mf < 2; mf++)
#pragma unroll
                for (int nf = 0; nf < 4; nf++)
                    mma_bf16(acc[mf][nf], ahi[mf], bhi[nf]);
#pragma unroll
            for (int mf = 0; mf < 2; mf++)
#pragma unroll
                for (int nf = 0; nf < 4; nf++)
                    mma_bf16(acc[mf][nf], ahi[mf], blo[nf]);
#pragma unroll
            for (int mf = 0; mf < 2; mf++)
#pragma unroll
                for (int nf = 0; nf < 4; nf++)
                    mma_bf16(acc[mf][nf], alo[mf], bhi[nf]);
        }
    }

    int g = lane >> 2, t = lane & 3;
#pragma unroll
    for (int mf = 0; mf < 2; mf++) {
#pragma unroll
        for (int nf = 0; nf < 4; nf++) {
            int m = m0 + wm * 32 + mf * 16 + g;
            int n = n0 + wn * 32 + nf * 8 + t * 2;
            float* p0 = g_c2 + (size_t)m * NDIM + n;
            float* p1 = g_c2 + (size_t)(m + 8) * NDIM + n;
            *(float2*)p0 = make_float2(acc[mf][nf][0], acc[mf][nf][1]);
            *(float2*)p1 = make_float2(acc[mf][nf][2], acc[mf][nf][3]);
        }
    }
}

// ---------------- bias + reshape + squash -> caps[B,1152,8] ----------------
__global__ void squash_caps_kernel(const float* __restrict__ pcb) {
    int idx = blockIdx.x * blockDim.x + threadIdx.x;
    if (idx >= BATCH * NCAPS) return;
    int b = idx / NCAPS, i = idx % NCAPS;
    float v[8];
    float mag = 0.f;
#pragma unroll
    for (int k = 0; k < 8; k++) {
        int f = i * 8 + k;
        int oc = f / NPOS, p = f % NPOS;
        float t = g_c2[(size_t)oc * NDIM + b * NPOS + p] + pcb[oc];
        v[k] = t;
        mag += t * t;
    }
    float scale = mag / ((1.f + mag) * sqrtf(mag));
#pragma unroll
    for (int k = 0; k < 8; k++) g_caps[(size_t)idx * 8 + k] = v[k] * scale;
}

// ---------------- u_hat: grid (1152, 16), block 160 ----------------
__global__ void uhat_kernel(const float* __restrict__ W) {
    int i = blockIdx.x;
    int b0 = blockIdx.y * 16;
    __shared__ float Ws[160 * 8];
    int t = threadIdx.x;
    for (int q = t; q < 1280; q += 160) Ws[q] = W[(size_t)i * 1280 + q];
    __syncthreads();
    float wr[8];
#pragma unroll
    for (int k = 0; k < 8; k++) wr[k] = Ws[t * 8 + k];
    for (int b = b0; b < b0 + 16; b++) {
        const float* cp = g_caps + ((size_t)b * NCAPS + i) * 8;
        float acc = 0.f;
#pragma unroll
        for (int k = 0; k < 8; k++) acc += wr[k] * __ldg(cp + k);
        g_uhat[((size_t)b * NCAPS + i) * 160 + t] = acc;
    }
}

// ---------------- fused dynamic routing, warp-cooperative, 512 threads ----------------
__global__ __launch_bounds__(512) void routing_kernel(const float* __restrict__ dc_bias,
                                                      float* __restrict__ out) {
    extern __shared__ float sm[];
    float* bs = sm;                  // [1152*10]
    float* swarp = sm + 11520;       // [16*160]
    float* vsm = sm + 11520 + 2560;  // [160]

    int b = blockIdx.x;
    int tid = threadIdx.x;
    int wid = tid >> 5, lane = tid & 31;
    int half = lane >> 4;
    const float* U = g_uhat + (size_t)b * (NCAPS * 160);

    for (int r = 0; r < 3; r++) {
        float vreg[5];
        if (r > 0) {
#pragma unroll
            for (int m = 0; m < 5; m++) vreg[m] = vsm[m * 32 + lane];
        }
        float sp[5] = {0.f, 0.f, 0.f, 0.f, 0.f};

        for (int i = wid; i < NCAPS; i += 16) {
            float u[5];
            const float* up = U + (size_t)i * 160;
#pragma unroll
            for (int m = 0; m < 5; m++) u[m] = up[m * 32 + lane];

            if (r == 0) {
#pragma unroll
                for (int m = 0; m < 5; m++) sp[m] += 0.1f * u[m];
                if ((lane & 15) == 0) {
#pragma unroll
                    for (int m = 0; m < 5; m++) bs[i * 10 + 2 * m + half] = 0.f;
                }
            } else {
                float bj[5];
#pragma unroll
                for (int m = 0; m < 5; m++) {
                    float t = u[m] * vreg[m];
                    t += __shfl_xor_sync(0xffffffff, t, 1);
                    t += __shfl_xor_sync(0xffffffff, t, 2);
                    t += __shfl_xor_sync(0xffffffff, t, 4);
                    t += __shfl_xor_sync(0xffffffff, t, 8);
                    bj[m] = bs[i * 10 + 2 * m + half] + t;
                }
                if (r == 1 && (lane & 15) == 0) {
#pragma unroll
                    for (int m = 0; m < 5; m++) bs[i * 10 + 2 * m + half] = bj[m];
                }
                float mx = bj[0];
#pragma unroll
                for (int m = 1; m < 5; m++) mx = fmaxf(mx, bj[m]);
                mx = fmaxf(mx, __shfl_xor_sync(0xffffffff, mx, 16));
                float es[5], ssum = 0.f;
#pragma unroll
                for (int m = 0; m < 5; m++) {
                    es[m] = expf(bj[m] - mx);
                    ssum += es[m];
                }
                ssum += __shfl_xor_sync(0xffffffff, ssum, 16);
                float inv = 1.f / ssum;
#pragma unroll
                for (int m = 0; m < 5; m++) sp[m] += (es[m] * inv) * u[m];
            }
        }
#pragma unroll
        for (int m = 0; m < 5; m++) swarp[wid * 160 + m * 32 + lane] = sp[m];
        __syncthreads();
        if (tid < 160) {
            float s = dc_bias[tid];
#pragma unroll
            for (int w = 0; w < 16; w++) s += swarp[w * 160 + tid];
            float sq = s * s;
#pragma unroll
            for (int o = 8; o > 0; o >>= 1)
                sq += __shfl_xor_sync(0xffffffff, sq, o);
            float scale = sq / ((1.f + sq) * sqrtf(sq));
            float v = s * scale;
            vsm[tid] = v;
            if (r == 2) out[b * 160 + tid] = v;
        }
        __syncthreads();
    }
}

// ---------------- launch ----------------
extern "C" void kernel_launch(void* const* d_in, const int* in_sizes, int n_in,
                              void* d_out, int out_size) {
    const float* x       = (const float*)d_in[0];
    const float* conv1_w = (const float*)d_in[1];
    const float* conv1_b = (const float*)d_in[2];
    const float* pc_w    = (const float*)d_in[3];
    const float* pc_b    = (const float*)d_in[4];
    const float* W       = (const float*)d_in[5];
    const float* dc_bias = (const float*)d_in[6];
    float* out = (float*)d_out;

    {
        dim3 grid(10, 256);
        conv1_kernel<<<grid, 256>>>(x, conv1_w, conv1_b);
    }

    {
        int total = MDIM * KDIM;
        convertA_kernel<<<(total + 255) / 256, 256>>>(pc_w);
    }

    {
        dim3 grid(81, NDIM);
        im2colB_kernel<<<grid, 128>>>();
    }

    {
        size_t smem = NSTAGE * STAGE_BYTES;  // 221184
        cudaFuncSetAttribute(gemm_mma_kernel,
                             cudaFuncAttributeMaxDynamicSharedMemorySize, (int)smem);
        dim3 grid(NDIM / 128, MDIM / 128);
        gemm_mma_kernel<<<grid, 512, smem>>>();
    }

    {
        int total = BATCH * NCAPS;
        squash_caps_kernel<<<(total + 255) / 256, 256>>>(pc_b);
    }

    {
        dim3 grid(NCAPS, 16);
        uhat_kernel<<<grid, 160>>>(W);
    }

    {
        size_t smem = (size_t)(11520 + 2560 + 160) * sizeof(float);  // 56960
        cudaFuncSetAttribute(routing_kernel,
                             cudaFuncAttributeMaxDynamicSharedMemorySize, (int)smem);
        routing_kernel<<<BATCH, 512, smem>>>(dc_bias, out);
    }
}